// round 17
// baseline (speedup 1.0000x reference)
#include <cuda_runtime.h>
#include <math.h>
#include <stdint.h>

#define Bn 64
#define Dn 256
#define Hn 512
#define Rn 32
#define CLIPV 50.0f

// Output layout (concatenation of the returned tuple, fp32):
//   v_new      [64,512]      @ 0
//   new_h      [64,512]      @ 32768
//   dU_new     [64,512,512]  @ 65536
//   new_trace_e[64,512]      @ 16842752
//   new_trace_E[64,512,512]  @ 16875520
#define OFF_V    ((size_t)0)
#define OFF_NH   ((size_t)32768)
#define OFF_DU   ((size_t)65536)
#define OFF_TEO  ((size_t)16842752)
#define OFF_TEE  ((size_t)16875520)

// Device-global scratch (allocation-free; fully rewritten every launch)
__device__ float g_suMod[Bn];
__device__ float g_sE;
__device__ float g_omU;
__device__ float g_sv[Hn];
__device__ float g_se[Hn];
__device__ float g_bias[Hn];

__device__ __forceinline__ float sigmoidf_(float x) {
    return 1.0f / (1.0f + expf(-x));
}
__device__ __forceinline__ float frcp_(float a) {
    float r;
    asm("rcp.approx.f32 %0, %1;" : "=f"(r) : "f"(a));
    return r;
}
__device__ __forceinline__ void cp_async16(uint32_t saddr, const float* gaddr) {
    asm volatile("cp.async.cg.shared.global [%0], [%1], 16;\n"
                 :: "r"(saddr), "l"(gaddr) : "memory");
}
__device__ __forceinline__ void cp_commit() {
    asm volatile("cp.async.commit_group;\n" ::: "memory");
}
__device__ __forceinline__ void cp_wait0() {
    asm volatile("cp.async.wait_group 0;\n" ::: "memory");
}

// ---------------------------------------------------------------------------
// Prep kernel: 66 blocks x 256 threads (~3us).
//   [0,64)  mod blocks: g_suMod[b] = sigmoid(tau_U)*mod[b] (+ scalars b==0).
//   [64,66) hoist blocks: g_sv/g_se/g_bias for all 512 i.
// ---------------------------------------------------------------------------
__global__ __launch_bounds__(256) void prep_kernel(
    const float* __restrict__ x, const float* __restrict__ h,
    const float* __restrict__ x2h_w, const float* __restrict__ x2h_b,
    const float* __restrict__ h2h_w, const float* __restrict__ h2h_b,
    const float* __restrict__ tau_v, const float* __restrict__ tau_e,
    const float* __restrict__ tau_U, const float* __restrict__ tau_E) {
    const int bx   = blockIdx.x;
    const int tid  = threadIdx.x;
    const int warp = tid >> 5;
    const int lane = tid & 31;

    if (bx < 64) {
        const int b = bx;
        __shared__ float sm[8];
        const float4* xb = (const float4*)(x + (size_t)b * Dn);
        const float4* hb = (const float4*)(h + (size_t)b * Hn);

        float acc = 0.f;
#pragma unroll
        for (int t = 0; t < 4; t++) {
            const int o = Hn + warp + 8 * t;
            const float4* xw = (const float4*)(x2h_w + (size_t)o * Dn);
            const float4* hw = (const float4*)(h2h_w + (size_t)o * Hn);
            float s = 0.f;
#pragma unroll
            for (int c = 0; c < 2; c++) {
                const float4 W4 = xw[c * 32 + lane];
                const float4 V4 = xb[c * 32 + lane];
                s = fmaf(W4.x, V4.x, s); s = fmaf(W4.y, V4.y, s);
                s = fmaf(W4.z, V4.z, s); s = fmaf(W4.w, V4.w, s);
            }
#pragma unroll
            for (int c = 0; c < 4; c++) {
                const float4 W4 = hw[c * 32 + lane];
                const float4 V4 = hb[c * 32 + lane];
                s = fmaf(W4.x, V4.x, s); s = fmaf(W4.y, V4.y, s);
                s = fmaf(W4.z, V4.z, s); s = fmaf(W4.w, V4.w, s);
            }
#pragma unroll
            for (int off = 16; off; off >>= 1)
                s += __shfl_xor_sync(0xffffffffu, s, off);
            if (lane == 0) acc += fmaxf(s + x2h_b[o] + h2h_b[o], 0.f);
        }
        if (lane == 0) sm[warp] = acc;
        __syncthreads();
        if (tid == 0) {
            float m = 0.f;
#pragma unroll
            for (int w = 0; w < 8; w++) m += sm[w];
            const float sU = sigmoidf_(tau_U[0]);
            g_suMod[b] = sU * m;
            if (b == 0) {
                g_sE  = sigmoidf_(tau_E[0]);
                g_omU = 1.0f - sU;
            }
        }
        return;
    }

    // hoist blocks: per-i sigmoids + bias
    const int i = (bx - 64) * 256 + tid;
    g_sv[i]   = sigmoidf_(tau_v[i]);
    g_se[i]   = sigmoidf_(tau_e[i]);
    g_bias[i] = x2h_b[i] + h2h_b[i];
}

// ---------------------------------------------------------------------------
// Main fused kernel: 4096 blocks x 128 threads, 16KB smem,
// __launch_bounds__(128, 8) -> 8 blocks/SM (128KB smem, 64 regs budget).
// Block owns rows (b, i0..i0+7) — ONE CONTIGUOUS 16KB dU segment; consecutive
// blocks share b and cover consecutive i0 -> contiguous 1MB DRAM sweeps and
// L2-broadcast h[b].
//  Phase A: cp.async the tile to smem (8 x 16B per thread), 1 barrier.
//  Phase B: warp w owns rows 2w, 2w+1: dv reduction (alpha/W/h via __ldg,
//           L2/L1-resident), butterfly, per-row scalars.
//  Phase C: epilogue with dU from smem; clip bounds computed INLINE from the
//           L1-hot alpha/W (rcp.approx) — no up/lo tables, epilogue L2
//           side-traffic halved vs R15. tE via __ldcs, outputs via __stcs.
// dU touches DRAM exactly once for the entire problem.
// 8 blocks/SM in different phases keep DRAM busy through the reduction.
// ---------------------------------------------------------------------------
__global__ __launch_bounds__(128, 8) void main_kernel(
    const float* __restrict__ x, const float* __restrict__ h,
    const float* __restrict__ v, const float* __restrict__ dU,
    const float* __restrict__ trace_e, const float* __restrict__ trace_E,
    const float* __restrict__ x2h_w, const float* __restrict__ h2h_w,
    const float* __restrict__ alpha, float* __restrict__ out) {
    extern __shared__ float sdu[];   // [8][512] = 16KB
    const int tid  = threadIdx.x;
    const int warp = tid >> 5;
    const int lane = tid & 31;
    const int b    = blockIdx.x >> 6;          // 0..63
    const int i0   = (blockIdx.x & 63) * 8;    // 0..504

    // ---- Phase A: stream the contiguous 16KB dU tile into smem ----
    const float* duBase = dU + ((size_t)b * Hn + i0) * Hn;  // 4096 floats
    const uint32_t sbase = (uint32_t)__cvta_generic_to_shared(sdu);
#pragma unroll
    for (int k = 0; k < 8; k++) {
        const int idx = tid + k * 128;         // float4 index 0..1023
        cp_async16(sbase + idx * 16, duBase + idx * 4);
    }
    cp_commit();
    cp_wait0();
    __syncthreads();

    const float sE    = g_sE;
    const float omU   = g_omU;
    const float suMod = g_suMod[b];

    const float4* h4p  = (const float4*)h + ((size_t)b << 7);
    const float4* te4p = (const float4*)trace_e + ((size_t)b << 7);
    const float4* x4p  = (const float4*)x + ((size_t)b << 6);
    const float4* tE4  = (const float4*)trace_E;
    float4* outDU = (float4*)(out + OFF_DU);
    float4* outTE = (float4*)(out + OFF_TEE);

#pragma unroll
    for (int half = 0; half < 2; half++) {
        const int r = warp * 2 + half;          // 0..7
        const int i = i0 + r;
        const size_t row  = (size_t)b * Hn + i;
        const size_t row4 = row << 7;
        const float* du = sdu + r * 512;

        const float4* a4p  = (const float4*)alpha + ((size_t)i << 7);
        const float4* w4p  = (const float4*)h2h_w + ((size_t)i << 7);
        const float4* xw4p = (const float4*)x2h_w + ((size_t)i << 6);

        // ---- Phase B: dv reduction (dU from smem; matrices from L2) ----
        float p0 = 0.f, p1 = 0.f, p2 = 0.f, p3 = 0.f;
#pragma unroll
        for (int c = 0; c < 4; c++) {
            const float4 D4 = *(const float4*)(du + c * 128 + lane * 4);
            const float4 A4 = __ldg(a4p + c * 32 + lane);
            const float4 W4 = __ldg(w4p + c * 32 + lane);
            const float4 H4 = __ldg(h4p + c * 32 + lane);
            p0 = fmaf(fmaf(fmaxf(A4.x, 0.f), D4.x, W4.x), H4.x, p0);
            p1 = fmaf(fmaf(fmaxf(A4.y, 0.f), D4.y, W4.y), H4.y, p1);
            p2 = fmaf(fmaf(fmaxf(A4.z, 0.f), D4.z, W4.z), H4.z, p2);
            p3 = fmaf(fmaf(fmaxf(A4.w, 0.f), D4.w, W4.w), H4.w, p3);
        }
#pragma unroll
        for (int c = 0; c < 2; c++) {
            const float4 XW = __ldg(xw4p + c * 32 + lane);
            const float4 X4 = __ldg(x4p + c * 32 + lane);
            p0 = fmaf(XW.x, X4.x, p0);
            p1 = fmaf(XW.y, X4.y, p1);
            p2 = fmaf(XW.z, X4.z, p2);
            p3 = fmaf(XW.w, X4.w, p3);
        }
        float p = (p0 + p1) + (p2 + p3);
#pragma unroll
        for (int off = 16; off; off >>= 1)
            p += __shfl_xor_sync(0xffffffffu, p, off);

        // per-row scalars (all lanes; broadcast loads)
        const float dv  = p + g_bias[i];
        const float vb  = __ldg(v + row);
        const float vn  = fmaf(g_sv[i], dv - vb, vb);
        const float nh  = fmaxf(vn, 0.f);
        const float teS = __ldg(trace_e + row);
        const float nte = fmaf(g_se[i], __ldg(h + row) - teS, teS);
        if (lane == 0) {
            out[OFF_V   + row] = vn;
            out[OFF_NH  + row] = nh;
            out[OFF_TEO + row] = nte;
        }

        // ---- Phase C: epilogue; clip bounds computed inline from the
        //      L1-hot alpha/W (no up/lo tables) ----
#pragma unroll
        for (int c = 0; c < 4; c++) {
            const float4 D4 = *(const float4*)(du + c * 128 + lane * 4);
            const float4 tE = __ldcs(&tE4[row4 + c * 32 + lane]);
            const float4 hh = __ldg(h4p + c * 32 + lane);
            const float4 te = __ldg(te4p + c * 32 + lane);
            const float4 A4 = __ldg(a4p + c * 32 + lane);   // L1 hit
            const float4 W4 = __ldg(w4p + c * 32 + lane);   // L1 hit

            float4 tOut, dOut;
            {
                const float rd = frcp_(fmaxf(A4.x, 0.f) + 1e-8f);
                const float o  = nh * te.x - nte * hh.x;
                tOut.x = fmaf(sE, o - tE.x, tE.x);
                float dn = fmaf(suMod, tOut.x, omU * D4.x);
                dn = fminf(dn,  fmaxf(CLIPV - W4.x, 0.f) * rd);
                dn = fmaxf(dn, -fmaxf(CLIPV + W4.x, 0.f) * rd);
                dOut.x = dn;
            }
            {
                const float rd = frcp_(fmaxf(A4.y, 0.f) + 1e-8f);
                const float o  = nh * te.y - nte * hh.y;
                tOut.y = fmaf(sE, o - tE.y, tE.y);
                float dn = fmaf(suMod, tOut.y, omU * D4.y);
                dn = fminf(dn,  fmaxf(CLIPV - W4.y, 0.f) * rd);
                dn = fmaxf(dn, -fmaxf(CLIPV + W4.y, 0.f) * rd);
                dOut.y = dn;
            }
            {
                const float rd = frcp_(fmaxf(A4.z, 0.f) + 1e-8f);
                const float o  = nh * te.z - nte * hh.z;
                tOut.z = fmaf(sE, o - tE.z, tE.z);
                float dn = fmaf(suMod, tOut.z, omU * D4.z);
                dn = fminf(dn,  fmaxf(CLIPV - W4.z, 0.f) * rd);
                dn = fmaxf(dn, -fmaxf(CLIPV + W4.z, 0.f) * rd);
                dOut.z = dn;
            }
            {
                const float rd = frcp_(fmaxf(A4.w, 0.f) + 1e-8f);
                const float o  = nh * te.w - nte * hh.w;
                tOut.w = fmaf(sE, o - tE.w, tE.w);
                float dn = fmaf(suMod, tOut.w, omU * D4.w);
                dn = fminf(dn,  fmaxf(CLIPV - W4.w, 0.f) * rd);
                dn = fmaxf(dn, -fmaxf(CLIPV + W4.w, 0.f) * rd);
                dOut.w = dn;
            }
            __stcs(&outTE[row4 + c * 32 + lane], tOut);
            __stcs(&outDU[row4 + c * 32 + lane], dOut);
        }
    }
}

extern "C" void kernel_launch(void* const* d_in, const int* in_sizes, int n_in,
                              void* d_out, int out_size) {
    const float* x       = (const float*)d_in[0];
    const float* h       = (const float*)d_in[1];
    const float* v       = (const float*)d_in[2];
    const float* dU      = (const float*)d_in[3];
    const float* trace_e = (const float*)d_in[4];
    const float* trace_E = (const float*)d_in[5];
    const float* x2h_w   = (const float*)d_in[6];
    const float* x2h_b   = (const float*)d_in[7];
    const float* h2h_w   = (const float*)d_in[8];
    const float* h2h_b   = (const float*)d_in[9];
    const float* alpha   = (const float*)d_in[10];
    const float* tau_v   = (const float*)d_in[11];
    const float* tau_e   = (const float*)d_in[12];
    const float* tau_U   = (const float*)d_in[13];
    const float* tau_E   = (const float*)d_in[14];
    float* out = (float*)d_out;

    prep_kernel<<<66, 256>>>(x, h, x2h_w, x2h_b, h2h_w, h2h_b,
                             tau_v, tau_e, tau_U, tau_E);
    const int smem = 8 * 512 * 4;  // 16KB dU tile
    main_kernel<<<4096, 128, smem>>>(x, h, v, dU, trace_e, trace_E,
                                     x2h_w, h2h_w, alpha, out);
}